// round 2
// baseline (speedup 1.0000x reference)
#include <cuda_runtime.h>
#include <math.h>

#define BB 8
#define TT 5
#define HH 512
#define WW 512
#define HW (HH*WW)
#define MID 16
#define NPIX (BB*HW)

// ---------------- scratch (no allocation allowed) ----------------
__device__ float g_acc[NPIX];                 // 8 MB
__device__ float g_h1[(size_t)NPIX*MID];      // 134 MB
__device__ float g_h2[(size_t)NPIX*MID];      // 134 MB
__device__ double g_dsum, g_dssq;
__device__ float g_mean, g_inv;
__device__ float g_w1f[144], g_s1[16];
__device__ float g_w2f[2304], g_s2[16];
__device__ float g_w3f[2304], g_s3[16];

// ---------------- prep: zero stats + fold BN into conv weights ----------------
__global__ void prep_kernel(
    const float* __restrict__ w1, const float* __restrict__ g1, const float* __restrict__ b1,
    const float* __restrict__ rm1, const float* __restrict__ rv1,
    const float* __restrict__ w2, const float* __restrict__ g2, const float* __restrict__ b2,
    const float* __restrict__ rm2, const float* __restrict__ rv2,
    const float* __restrict__ w3, const float* __restrict__ g3, const float* __restrict__ b3,
    const float* __restrict__ rm3, const float* __restrict__ rv3)
{
    int tid = threadIdx.x;
    if (tid == 0) { g_dsum = 0.0; g_dssq = 0.0; }

    // conv1: sum over T input channels (motion broadcast), fold BN scale
    for (int i = tid; i < 144; i += 256) {
        int o = i / 9, k = i % 9;
        float sc = g1[o] / sqrtf(rv1[o] + 1e-5f);
        float s = 0.f;
        #pragma unroll
        for (int t = 0; t < TT; t++) s += w1[(o * TT + t) * 9 + k];
        g_w1f[i] = sc * s;
    }
    if (tid < 16) {
        float sc1 = g1[tid] / sqrtf(rv1[tid] + 1e-5f);
        g_s1[tid] = b1[tid] - rm1[tid] * sc1;
        float sc2 = g2[tid] / sqrtf(rv2[tid] + 1e-5f);
        g_s2[tid] = b2[tid] - rm2[tid] * sc2;
        float sc3 = g3[tid] / sqrtf(rv3[tid] + 1e-5f);
        g_s3[tid] = b3[tid] - rm3[tid] * sc3;
    }
    // conv2/conv3 folded weights in [tap][ci][co] layout (co contiguous for LDS.128)
    for (int i = tid; i < 2304; i += 256) {
        int k = i >> 8, ci = (i >> 4) & 15, co = i & 15;
        float sc2 = g2[co] / sqrtf(rv2[co] + 1e-5f);
        g_w2f[i] = sc2 * w2[(co * 16 + ci) * 9 + k];
        float sc3 = g3[co] / sqrtf(rv3[co] + 1e-5f);
        g_w3f[i] = sc3 * w3[(co * 16 + ci) * 9 + k];
    }
}

// ---------------- A: acc = sum|raw_diff| + mean/var reduction ----------------
__global__ void accum_kernel(const float* __restrict__ rd)
{
    int i = blockIdx.x * 256 + threadIdx.x;        // over NPIX/4 = 524288
    int b = i >> 16;                               // HW/4 = 65536 float4 per image
    int r = i & 65535;
    const float4* p = (const float4*)rd;
    float4 a = make_float4(0.f, 0.f, 0.f, 0.f);
    #pragma unroll
    for (int t = 0; t < TT - 1; t++) {
        float4 v = p[((size_t)(b * (TT - 1) + t)) * 65536 + r];
        a.x += fabsf(v.x); a.y += fabsf(v.y); a.z += fabsf(v.z); a.w += fabsf(v.w);
    }
    ((float4*)g_acc)[i] = a;

    double ls  = (double)a.x + (double)a.y + (double)a.z + (double)a.w;
    double lss = (double)a.x * a.x + (double)a.y * a.y + (double)a.z * a.z + (double)a.w * a.w;
    #pragma unroll
    for (int o = 16; o > 0; o >>= 1) {
        ls  += __shfl_down_sync(0xffffffffu, ls,  o);
        lss += __shfl_down_sync(0xffffffffu, lss, o);
    }
    __shared__ double ss[8], sq[8];
    int wid = threadIdx.x >> 5, lane = threadIdx.x & 31;
    if (lane == 0) { ss[wid] = ls; sq[wid] = lss; }
    __syncthreads();
    if (threadIdx.x == 0) {
        double s = 0.0, q = 0.0;
        #pragma unroll
        for (int w = 0; w < 8; w++) { s += ss[w]; q += sq[w]; }
        atomicAdd(&g_dsum, s);
        atomicAdd(&g_dssq, q);
    }
}

__global__ void finalize_kernel()
{
    double n = (double)NPIX;
    double mean = g_dsum / n;
    double var = (g_dssq - g_dsum * g_dsum / n) / (n - 1.0);
    double sd = sqrt(var);
    g_mean = (float)mean;
    g_inv = (float)(1.0 / (sd + 1e-6));
}

// ---------------- conv1: 1->16 chan, 3x3 d1, normalize-on-load, BN+ReLU ----------------
__global__ void conv1_kernel()
{
    __shared__ float sw[144], sb[16];
    int tid = threadIdx.x;
    if (tid < 144) sw[tid] = g_w1f[tid];
    if (tid < 16)  sb[tid] = g_s1[tid];
    __syncthreads();

    int p = blockIdx.x * 256 + tid;
    int b = p >> 18;
    int rem = p & (HW - 1);
    int y = rem >> 9, x = rem & 511;
    float mean = g_mean, inv = g_inv;

    float m[9];
    #pragma unroll
    for (int ky = 0; ky < 3; ky++) {
        #pragma unroll
        for (int kx = 0; kx < 3; kx++) {
            int yy = y + ky - 1, xx = x + kx - 1;
            bool ok = (yy >= 0) & (yy < HH) & (xx >= 0) & (xx < WW);
            m[ky * 3 + kx] = ok ? (g_acc[(b << 18) + (yy << 9) + xx] - mean) * inv : 0.f;
        }
    }
    float v[16];
    #pragma unroll
    for (int o = 0; o < 16; o++) {
        float s = sb[o];
        #pragma unroll
        for (int k = 0; k < 9; k++) s = fmaf(sw[o * 9 + k], m[k], s);
        v[o] = fmaxf(s, 0.f);
    }
    float4* out = (float4*)(g_h1 + (size_t)p * 16);
    out[0] = make_float4(v[0],  v[1],  v[2],  v[3]);
    out[1] = make_float4(v[4],  v[5],  v[6],  v[7]);
    out[2] = make_float4(v[8],  v[9],  v[10], v[11]);
    out[3] = make_float4(v[12], v[13], v[14], v[15]);
}

// ---------------- conv2/conv3: 16->16 chan, 3x3 dilated, BN+ReLU, NHWC ----------------
// 2 pixels (x, x+32) per thread; weights in smem, co-contiguous -> LDS.128
template<int DIL>
__global__ __launch_bounds__(128) void conv16_kernel()
{
    const float* __restrict__ in  = (DIL == 2) ? g_h1 : g_h2;
    float*       __restrict__ out = (DIL == 2) ? g_h2 : g_h1;
    const float* wf = (DIL == 2) ? g_w2f : g_w3f;
    const float* sh = (DIL == 2) ? g_s2  : g_s3;

    __shared__ float sw[2304];
    __shared__ float sb[16];
    int tid = threadIdx.y * 32 + threadIdx.x;
    for (int i = tid; i < 2304; i += 128) sw[i] = wf[i];
    if (tid < 16) sb[tid] = sh[tid];
    __syncthreads();

    int x0 = blockIdx.x * 64 + threadIdx.x;
    int y  = blockIdx.y * 4 + threadIdx.y;
    int b  = blockIdx.z;

    float a0[16], a1[16];
    #pragma unroll
    for (int c = 0; c < 16; c++) { a0[c] = 0.f; a1[c] = 0.f; }

    #pragma unroll
    for (int ky = 0; ky < 3; ky++) {
        int yy = y + (ky - 1) * DIL;
        if (yy < 0 || yy >= HH) continue;
        size_t rowbase = ((size_t)b << 18) + ((size_t)yy << 9);
        #pragma unroll
        for (int kx = 0; kx < 3; kx++) {
            int k = ky * 3 + kx;
            int xx0 = x0 + (kx - 1) * DIL;
            int xx1 = xx0 + 32;
            bool v0 = (xx0 >= 0) & (xx0 < WW);
            bool v1 = (xx1 >= 0) & (xx1 < WW);
            const float4* q0 = (const float4*)(in + (rowbase + xx0) * 16);
            const float4* q1 = (const float4*)(in + (rowbase + xx1) * 16);
            float f0[16], f1[16];
            #pragma unroll
            for (int c = 0; c < 4; c++) {
                float4 t0 = v0 ? q0[c] : make_float4(0.f, 0.f, 0.f, 0.f);
                float4 t1 = v1 ? q1[c] : make_float4(0.f, 0.f, 0.f, 0.f);
                f0[4 * c + 0] = t0.x; f0[4 * c + 1] = t0.y; f0[4 * c + 2] = t0.z; f0[4 * c + 3] = t0.w;
                f1[4 * c + 0] = t1.x; f1[4 * c + 1] = t1.y; f1[4 * c + 2] = t1.z; f1[4 * c + 3] = t1.w;
            }
            const float* wk = sw + k * 256;
            #pragma unroll
            for (int ci = 0; ci < 16; ci++) {
                float u0 = f0[ci], u1 = f1[ci];
                const float* wr = wk + ci * 16;
                #pragma unroll
                for (int co = 0; co < 16; co++) {
                    float w = wr[co];
                    a0[co] = fmaf(w, u0, a0[co]);
                    a1[co] = fmaf(w, u1, a1[co]);
                }
            }
        }
    }

    size_t ob = ((size_t)b << 18) + ((size_t)y << 9);
    float4* o0 = (float4*)(out + (ob + x0) * 16);
    float4* o1 = (float4*)(out + (ob + x0 + 32) * 16);
    #pragma unroll
    for (int c = 0; c < 4; c++) {
        o0[c] = make_float4(fmaxf(a0[4*c+0] + sb[4*c+0], 0.f), fmaxf(a0[4*c+1] + sb[4*c+1], 0.f),
                            fmaxf(a0[4*c+2] + sb[4*c+2], 0.f), fmaxf(a0[4*c+3] + sb[4*c+3], 0.f));
        o1[c] = make_float4(fmaxf(a1[4*c+0] + sb[4*c+0], 0.f), fmaxf(a1[4*c+1] + sb[4*c+1], 0.f),
                            fmaxf(a1[4*c+2] + sb[4*c+2], 0.f), fmaxf(a1[4*c+3] + sb[4*c+3], 0.f));
    }
}

// ---------------- conv4 (1x1, 16->45) + sigmoid + dynamic 3x3 filtering ----------------
__global__ __launch_bounds__(128) void final_kernel(
    const float* __restrict__ x, const float* __restrict__ w4,
    const float* __restrict__ biasp, float* __restrict__ out)
{
    __shared__ float sw[720];
    int tid = threadIdx.x;
    for (int i = tid; i < 720; i += 128) sw[i] = w4[i];
    __syncthreads();

    int p = blockIdx.x * 128 + tid;
    int b = p >> 18;
    int rem = p & (HW - 1);
    int y = rem >> 9, xc = rem & 511;

    float h[16];
    const float4* hp = (const float4*)(g_h1 + (size_t)p * 16);
    #pragma unroll
    for (int c = 0; c < 4; c++) {
        float4 t = hp[c];
        h[4*c+0] = t.x; h[4*c+1] = t.y; h[4*c+2] = t.z; h[4*c+3] = t.w;
    }
    float bias = biasp[0];

    #pragma unroll
    for (int t = 0; t < TT; t++) {
        float r[9];
        #pragma unroll
        for (int j = 0; j < 9; j++) {
            const float* wr = sw + (t * 9 + j) * 16;
            float s = 0.f;
            #pragma unroll
            for (int ci = 0; ci < 16; ci++) s = fmaf(wr[ci], h[ci], s);
            r[j] = s;
        }
        const float* xb = x + ((size_t)(b * TT + t) << 18);
        float o = 0.f;
        #pragma unroll
        for (int dy = 0; dy < 3; dy++) {
            int yy = y + dy - 1;
            #pragma unroll
            for (int dx = 0; dx < 3; dx++) {
                int xx = xc + dx - 1;
                bool ok = (yy >= 0) & (yy < HH) & (xx >= 0) & (xx < WW);
                float xv = ok ? xb[(yy << 9) + xx] : 0.f;
                float z = r[dy * 3 + dx] + bias;
                float ker = 10.f / (1.f + __expf(-z)) + 0.1f;
                o = fmaf(ker, xv, o);
            }
        }
        out[((size_t)(b * TT + t) << 18) + rem] = o;
    }
}

// ---------------- launch ----------------
extern "C" void kernel_launch(void* const* d_in, const int* in_sizes, int n_in,
                              void* d_out, int out_size)
{
    const float* x_aligned = (const float*)d_in[0];
    const float* raw_diff  = (const float*)d_in[1];
    const float* w1  = (const float*)d_in[2];
    const float* g1  = (const float*)d_in[3];
    const float* b1  = (const float*)d_in[4];
    const float* rm1 = (const float*)d_in[5];
    const float* rv1 = (const float*)d_in[6];
    const float* w2  = (const float*)d_in[7];
    const float* g2  = (const float*)d_in[8];
    const float* b2  = (const float*)d_in[9];
    const float* rm2 = (const float*)d_in[10];
    const float* rv2 = (const float*)d_in[11];
    const float* w3  = (const float*)d_in[12];
    const float* g3  = (const float*)d_in[13];
    const float* b3  = (const float*)d_in[14];
    const float* rm3 = (const float*)d_in[15];
    const float* rv3 = (const float*)d_in[16];
    const float* w4  = (const float*)d_in[17];
    const float* bias = (const float*)d_in[18];
    float* out = (float*)d_out;

    prep_kernel<<<1, 256>>>(w1, g1, b1, rm1, rv1, w2, g2, b2, rm2, rv2,
                            w3, g3, b3, rm3, rv3);
    accum_kernel<<<NPIX / 4 / 256, 256>>>(raw_diff);
    finalize_kernel<<<1, 1>>>();
    conv1_kernel<<<NPIX / 256, 256>>>();
    {
        dim3 blk(32, 4);
        dim3 grd(WW / 64, HH / 4, BB);
        conv16_kernel<2><<<grd, blk>>>();
        conv16_kernel<4><<<grd, blk>>>();
    }
    final_kernel<<<NPIX / 128, 128>>>(x_aligned, w4, bias, out);
}

// round 4
// speedup vs baseline: 2.7315x; 2.7315x over previous
#include <cuda_runtime.h>
#include <cuda_fp16.h>
#include <math.h>
#include <stdint.h>

#define BB 8
#define TT 5
#define HH 512
#define WW 512
#define HW (HH*WW)
#define MID 16
#define NPIX (BB*HW)

// ---------------- scratch (no allocation allowed) ----------------
__device__ float  g_acc[NPIX];                    // 8 MB
__device__ __half g_h1[(size_t)NPIX*MID];         // 67 MB
__device__ __half g_h2[(size_t)NPIX*MID];         // 67 MB
__device__ double g_dsum, g_dssq;
__device__ float g_mean, g_inv;
__device__ float g_w1f[144], g_s1[16];
__device__ uint32_t g_wF2[1152];                  // B fragments (half2) conv2
__device__ uint32_t g_wF3[1152];                  // B fragments (half2) conv3
__device__ float g_s2[16], g_s3[16];

// ---------------- PTX helpers ----------------
__device__ __forceinline__ uint32_t s2u(const void* p) {
    uint32_t a;
    asm("{ .reg .u64 t; cvta.to.shared.u64 t, %1; cvt.u32.u64 %0, t; }" : "=r"(a) : "l"(p));
    return a;
}
__device__ __forceinline__ void cpasync16(uint32_t dst, const void* src) {
    asm volatile("cp.async.cg.shared.global [%0], [%1], 16;" :: "r"(dst), "l"(src));
}
__device__ __forceinline__ void cp_commit() {
    asm volatile("cp.async.commit_group;" ::: "memory");
}
template<int N> __device__ __forceinline__ void cp_wait() {
    asm volatile("cp.async.wait_group %0;" :: "n"(N) : "memory");
}
__device__ __forceinline__ void sts_zero16(uint32_t dst) {
    asm volatile("st.shared.v4.u32 [%0], {%1,%1,%1,%1};" :: "r"(dst), "r"(0u) : "memory");
}
__device__ __forceinline__ void ldmatrix_x4(uint32_t& r0, uint32_t& r1, uint32_t& r2,
                                            uint32_t& r3, uint32_t addr) {
    asm volatile("ldmatrix.sync.aligned.m8n8.x4.shared.b16 {%0,%1,%2,%3}, [%4];"
                 : "=r"(r0), "=r"(r1), "=r"(r2), "=r"(r3) : "r"(addr));
}
__device__ __forceinline__ void mma_f16(float* d, uint32_t a0, uint32_t a1, uint32_t a2,
                                        uint32_t a3, uint32_t b0, uint32_t b1) {
    asm volatile(
        "mma.sync.aligned.m16n8k16.row.col.f32.f16.f16.f32 "
        "{%0,%1,%2,%3}, {%4,%5,%6,%7}, {%8,%9}, {%0,%1,%2,%3};"
        : "+f"(d[0]), "+f"(d[1]), "+f"(d[2]), "+f"(d[3])
        : "r"(a0), "r"(a1), "r"(a2), "r"(a3), "r"(b0), "r"(b1));
}
__device__ __forceinline__ uint32_t pack_h2(float a, float b) {
    __half2 h = __floats2half2_rn(a, b);
    return *reinterpret_cast<uint32_t*>(&h);
}

// ---------------- prep: fold BN into conv weights, build B fragments ----------------
__global__ void prep_kernel(
    const float* __restrict__ w1, const float* __restrict__ g1, const float* __restrict__ b1,
    const float* __restrict__ rm1, const float* __restrict__ rv1,
    const float* __restrict__ w2, const float* __restrict__ g2, const float* __restrict__ b2,
    const float* __restrict__ rm2, const float* __restrict__ rv2,
    const float* __restrict__ w3, const float* __restrict__ g3, const float* __restrict__ b3,
    const float* __restrict__ rm3, const float* __restrict__ rv3)
{
    int tid = threadIdx.x;
    if (tid == 0) { g_dsum = 0.0; g_dssq = 0.0; }

    for (int i = tid; i < 144; i += 256) {
        int o = i / 9, k = i % 9;
        float sc = g1[o] / sqrtf(rv1[o] + 1e-5f);
        float s = 0.f;
        #pragma unroll
        for (int t = 0; t < TT; t++) s += w1[(o * TT + t) * 9 + k];
        g_w1f[i] = sc * s;
    }
    if (tid < 16) {
        float sc1 = g1[tid] / sqrtf(rv1[tid] + 1e-5f);
        g_s1[tid] = b1[tid] - rm1[tid] * sc1;
        float sc2 = g2[tid] / sqrtf(rv2[tid] + 1e-5f);
        g_s2[tid] = b2[tid] - rm2[tid] * sc2;
        float sc3 = g3[tid] / sqrtf(rv3[tid] + 1e-5f);
        g_s3[tid] = b3[tid] - rm3[tid] * sc3;
    }
    // B fragments for m16n8k16: thread t, reg r(k-half), ngroup g, tap:
    //   co = 8g + t/4 ; k pair = (t%4)*2 + 8r, +1 ; value = bnScale[co]*w[co][k][tap]
    for (int i = tid; i < 1152; i += 256) {
        int t = i & 31, r = (i >> 5) & 1, g = (i >> 6) & 1, tap = i >> 7;
        int co = (g << 3) + (t >> 2);
        int k0 = (t & 3) * 2 + (r << 3);
        float sc2 = g2[co] / sqrtf(rv2[co] + 1e-5f);
        g_wF2[i] = pack_h2(sc2 * w2[((co * 16 + k0) * 9) + tap],
                           sc2 * w2[((co * 16 + k0 + 1) * 9) + tap]);
        float sc3 = g3[co] / sqrtf(rv3[co] + 1e-5f);
        g_wF3[i] = pack_h2(sc3 * w3[((co * 16 + k0) * 9) + tap],
                           sc3 * w3[((co * 16 + k0 + 1) * 9) + tap]);
    }
}

// ---------------- acc = sum|raw_diff| + mean/var reduction ----------------
__global__ void accum_kernel(const float* __restrict__ rd)
{
    int i = blockIdx.x * 256 + threadIdx.x;
    int b = i >> 16;
    int r = i & 65535;
    const float4* p = (const float4*)rd;
    float4 a = make_float4(0.f, 0.f, 0.f, 0.f);
    #pragma unroll
    for (int t = 0; t < TT - 1; t++) {
        float4 v = p[((size_t)(b * (TT - 1) + t)) * 65536 + r];
        a.x += fabsf(v.x); a.y += fabsf(v.y); a.z += fabsf(v.z); a.w += fabsf(v.w);
    }
    ((float4*)g_acc)[i] = a;

    double ls  = (double)a.x + (double)a.y + (double)a.z + (double)a.w;
    double lss = (double)a.x * a.x + (double)a.y * a.y + (double)a.z * a.z + (double)a.w * a.w;
    #pragma unroll
    for (int o = 16; o > 0; o >>= 1) {
        ls  += __shfl_down_sync(0xffffffffu, ls,  o);
        lss += __shfl_down_sync(0xffffffffu, lss, o);
    }
    __shared__ double ss[8], sq[8];
    int wid = threadIdx.x >> 5, lane = threadIdx.x & 31;
    if (lane == 0) { ss[wid] = ls; sq[wid] = lss; }
    __syncthreads();
    if (threadIdx.x == 0) {
        double s = 0.0, q = 0.0;
        #pragma unroll
        for (int w = 0; w < 8; w++) { s += ss[w]; q += sq[w]; }
        atomicAdd(&g_dsum, s);
        atomicAdd(&g_dssq, q);
    }
}

__global__ void finalize_kernel()
{
    double n = (double)NPIX;
    double mean = g_dsum / n;
    double var = (g_dssq - g_dsum * g_dsum / n) / (n - 1.0);
    double sd = sqrt(var);
    g_mean = (float)mean;
    g_inv = (float)(1.0 / (sd + 1e-6));
}

// ---------------- conv1: 1->16 chan, 3x3 d1, fp16 NHWC output ----------------
__global__ void conv1_kernel()
{
    __shared__ float sw[144], sb[16];
    int tid = threadIdx.x;
    if (tid < 144) sw[tid] = g_w1f[tid];
    if (tid < 16)  sb[tid] = g_s1[tid];
    __syncthreads();

    int p = blockIdx.x * 256 + tid;
    int b = p >> 18;
    int rem = p & (HW - 1);
    int y = rem >> 9, x = rem & 511;
    float mean = g_mean, inv = g_inv;

    float m[9];
    #pragma unroll
    for (int ky = 0; ky < 3; ky++) {
        #pragma unroll
        for (int kx = 0; kx < 3; kx++) {
            int yy = y + ky - 1, xx = x + kx - 1;
            bool ok = (yy >= 0) & (yy < HH) & (xx >= 0) & (xx < WW);
            m[ky * 3 + kx] = ok ? (g_acc[(b << 18) + (yy << 9) + xx] - mean) * inv : 0.f;
        }
    }
    float v[16];
    #pragma unroll
    for (int o = 0; o < 16; o++) {
        float s = sb[o];
        #pragma unroll
        for (int k = 0; k < 9; k++) s = fmaf(sw[o * 9 + k], m[k], s);
        v[o] = fmaxf(s, 0.f);
    }
    uint4* out = (uint4*)(g_h1 + (size_t)p * 16);
    out[0] = make_uint4(pack_h2(v[0], v[1]),  pack_h2(v[2], v[3]),
                        pack_h2(v[4], v[5]),  pack_h2(v[6], v[7]));
    out[1] = make_uint4(pack_h2(v[8], v[9]),  pack_h2(v[10], v[11]),
                        pack_h2(v[12], v[13]), pack_h2(v[14], v[15]));
}

// ---------------- conv2/conv3 via ldmatrix + mma.sync (fp16 in, fp32 acc) ----------------
// CTA: 128-pixel x-strip x 64 output rows, 256 threads (8 warps x 16-pixel tiles).
// SMEM ring of input rows; pixel stride 48B (32B data + 16B pad) -> conflict-free ldmatrix.
template<int DIL>
__global__ __launch_bounds__(256) void conv16_hmma_kernel()
{
    constexpr int XW = 128, YR = 64, PD = 2;
    constexpr int RING = 2 * DIL + PD + 1;       // 7 (D=2) / 11 (D=4)
    constexpr int SEGPX = XW + 2 * DIL;
    constexpr int SLOTB = SEGPX * 48;

    const __half* __restrict__ in  = (DIL == 2) ? g_h1 : g_h2;
    __half*       __restrict__ out = (DIL == 2) ? g_h2 : g_h1;
    const uint32_t* __restrict__ wF = (DIL == 2) ? g_wF2 : g_wF3;
    const float* __restrict__ sB   = (DIL == 2) ? g_s2  : g_s3;

    extern __shared__ char smem[];
    uint32_t sbase = s2u(smem);
    int tid = threadIdx.x;
    int warp = tid >> 5, lane = tid & 31;
    int x0 = blockIdx.x * XW;
    int y0 = blockIdx.y * YR;
    int b  = blockIdx.z;
    const __half* gin = in + (((size_t)b) << 18) * 16;

    // weight B-fragments -> registers (coalesced: stride-32 with lane offset)
    uint32_t bw[9][2][2];
    #pragma unroll
    for (int tap = 0; tap < 9; tap++)
        #pragma unroll
        for (int g = 0; g < 2; g++)
            #pragma unroll
            for (int r = 0; r < 2; r++)
                bw[tap][g][r] = wF[(((tap << 1) + g) << 1 | r) * 32 + lane];

    float bc0[2], bc1[2];
    #pragma unroll
    for (int g = 0; g < 2; g++) {
        int c = (g << 3) + ((lane & 3) << 1);
        bc0[g] = sB[c]; bc1[g] = sB[c + 1];
    }

    // ldmatrix per-thread source row: pixel within tile + k-half select
    int prow = warp * 16 + (lane & 7) + ((lane >> 3) & 1) * 8;
    int sel16 = ((lane >> 4) & 1) * 16;

    auto load_row = [&](int idx) {
        if (idx <= YR - 1 + 2 * DIL) {
            int r = y0 - DIL + idx;
            uint32_t dbase = sbase + (idx % RING) * SLOTB;
            bool rok = (r >= 0) & (r < HH);
            const __half* grow = gin + (((size_t)r) << 9) * 16;
            for (int c = tid; c < SEGPX * 2; c += 256) {
                int s = c >> 1, part = c & 1;
                int x = x0 - DIL + s;
                uint32_t dst = dbase + s * 48 + part * 16;
                if (rok && (unsigned)x < (unsigned)WW)
                    cpasync16(dst, grow + x * 16 + part * 8);
                else
                    sts_zero16(dst);
            }
        }
        cp_commit();
    };

    for (int idx = 0; idx <= 2 * DIL + PD; idx++) load_row(idx);

    for (int i = 0; i < YR; i++) {
        cp_wait<PD>();
        __syncthreads();

        float d[2][4];
        #pragma unroll
        for (int g = 0; g < 2; g++)
            #pragma unroll
            for (int r = 0; r < 4; r++) d[g][r] = 0.f;

        #pragma unroll
        for (int ky = 0; ky < 3; ky++) {
            uint32_t abase = sbase + ((i + ky * DIL) % RING) * SLOTB;
            #pragma unroll
            for (int kx = 0; kx < 3; kx++) {
                uint32_t a0, a1, a2, a3;
                ldmatrix_x4(a0, a1, a2, a3, abase + (prow + kx * DIL) * 48 + sel16);
                int tap = ky * 3 + kx;
                mma_f16(d[0], a0, a1, a2, a3, bw[tap][0][0], bw[tap][0][1]);
                mma_f16(d[1], a0, a1, a2, a3, bw[tap][1][0], bw[tap][1][1]);
            }
        }

        __half* orow = out + ((((size_t)b << 18) + ((size_t)(y0 + i) << 9) + x0 + warp * 16)) * 16;
        int px = (lane >> 2);
        #pragma unroll
        for (int g = 0; g < 2; g++) {
            int c = (g << 3) + ((lane & 3) << 1);
            uint32_t lo = pack_h2(fmaxf(d[g][0] + bc0[g], 0.f), fmaxf(d[g][1] + bc1[g], 0.f));
            uint32_t hi = pack_h2(fmaxf(d[g][2] + bc0[g], 0.f), fmaxf(d[g][3] + bc1[g], 0.f));
            *(uint32_t*)(orow + px * 16 + c)       = lo;
            *(uint32_t*)(orow + (px + 8) * 16 + c) = hi;
        }

        __syncthreads();
        load_row(i + 2 * DIL + PD + 1);
    }
}

// ---------------- conv4 (1x1, 16->45) + sigmoid + dynamic 3x3 filtering ----------------
__global__ __launch_bounds__(128) void final_kernel(
    const float* __restrict__ x, const float* __restrict__ w4,
    const float* __restrict__ biasp, float* __restrict__ out)
{
    __shared__ float sw[720];
    int tid = threadIdx.x;
    for (int i = tid; i < 720; i += 128) sw[i] = w4[i];
    __syncthreads();

    int p = blockIdx.x * 128 + tid;
    int b = p >> 18;
    int rem = p & (HW - 1);
    int y = rem >> 9, xc = rem & 511;

    float h[16];
    const uint4* hp = (const uint4*)(g_h1 + (size_t)p * 16);
    #pragma unroll
    for (int q = 0; q < 2; q++) {
        uint4 u = hp[q];
        uint32_t w[4] = {u.x, u.y, u.z, u.w};
        #pragma unroll
        for (int j = 0; j < 4; j++) {
            float2 f = __half22float2(*reinterpret_cast<__half2*>(&w[j]));
            h[q * 8 + j * 2]     = f.x;
            h[q * 8 + j * 2 + 1] = f.y;
        }
    }
    float bias = biasp[0];

    #pragma unroll
    for (int t = 0; t < TT; t++) {
        float r[9];
        #pragma unroll
        for (int j = 0; j < 9; j++) {
            const float* wr = sw + (t * 9 + j) * 16;
            float s = 0.f;
            #pragma unroll
            for (int ci = 0; ci < 16; ci++) s = fmaf(wr[ci], h[ci], s);
            r[j] = s;
        }
        const float* xb = x + ((size_t)(b * TT + t) << 18);
        float o = 0.f;
        #pragma unroll
        for (int dy = 0; dy < 3; dy++) {
            int yy = y + dy - 1;
            #pragma unroll
            for (int dx = 0; dx < 3; dx++) {
                int xx = xc + dx - 1;
                bool ok = (yy >= 0) & (yy < HH) & (xx >= 0) & (xx < WW);
                float xv = ok ? xb[(yy << 9) + xx] : 0.f;
                float z = r[dy * 3 + dx] + bias;
                float ker = 10.f / (1.f + __expf(-z)) + 0.1f;
                o = fmaf(ker, xv, o);
            }
        }
        out[((size_t)(b * TT + t) << 18) + rem] = o;
    }
}

// ---------------- launch ----------------
extern "C" void kernel_launch(void* const* d_in, const int* in_sizes, int n_in,
                              void* d_out, int out_size)
{
    const float* x_aligned = (const float*)d_in[0];
    const float* raw_diff  = (const float*)d_in[1];
    const float* w1  = (const float*)d_in[2];
    const float* g1  = (const float*)d_in[3];
    const float* b1  = (const float*)d_in[4];
    const float* rm1 = (const float*)d_in[5];
    const float* rv1 = (const float*)d_in[6];
    const float* w2  = (const float*)d_in[7];
    const float* g2  = (const float*)d_in[8];
    const float* b2  = (const float*)d_in[9];
    const float* rm2 = (const float*)d_in[10];
    const float* rv2 = (const float*)d_in[11];
    const float* w3  = (const float*)d_in[12];
    const float* g3  = (const float*)d_in[13];
    const float* b3  = (const float*)d_in[14];
    const float* rm3 = (const float*)d_in[15];
    const float* rv3 = (const float*)d_in[16];
    const float* w4  = (const float*)d_in[17];
    const float* bias = (const float*)d_in[18];
    float* out = (float*)d_out;

    const int SMEM2 = 7  * (132 * 48);   // 44,352 B
    const int SMEM4 = 11 * (136 * 48);   // 71,808 B
    static bool attr_done = false;
    if (!attr_done) {
        cudaFuncSetAttribute(conv16_hmma_kernel<2>, cudaFuncAttributeMaxDynamicSharedMemorySize, SMEM2);
        cudaFuncSetAttribute(conv16_hmma_kernel<4>, cudaFuncAttributeMaxDynamicSharedMemorySize, SMEM4);
        attr_done = true;
    }

    prep_kernel<<<1, 256>>>(w1, g1, b1, rm1, rv1, w2, g2, b2, rm2, rv2,
                            w3, g3, b3, rm3, rv3);
    accum_kernel<<<NPIX / 4 / 256, 256>>>(raw_diff);
    finalize_kernel<<<1, 1>>>();
    conv1_kernel<<<NPIX / 256, 256>>>();
    {
        dim3 grd(WW / 128, HH / 64, BB);   // (4, 8, 8)
        conv16_hmma_kernel<2><<<grd, 256, SMEM2>>>();
        conv16_hmma_kernel<4><<<grd, 256, SMEM4>>>();
    }
    final_kernel<<<NPIX / 128, 128>>>(x_aligned, w4, bias, out);
}

// round 7
// speedup vs baseline: 3.2786x; 1.2003x over previous
#include <cuda_runtime.h>
#include <cuda_fp16.h>
#include <math.h>
#include <stdint.h>

#define BB 8
#define TT 5
#define HH 512
#define WW 512
#define HW (HH*WW)
#define MID 16
#define NPIX (BB*HW)

// ---------------- scratch (no allocation allowed) ----------------
__device__ float  g_acc[NPIX];                    // 8 MB
__device__ __half g_h1[(size_t)NPIX*MID];         // 67 MB
__device__ __half g_h2[(size_t)NPIX*MID];         // 67 MB
__device__ double g_dsum, g_dssq;
__device__ float g_mean, g_inv;
__device__ float g_w1f[144], g_s1[16];
__device__ uint32_t g_wF2[1152];                  // B fragments (half2) conv2
__device__ uint32_t g_wF3[1152];                  // B fragments (half2) conv3
__device__ uint32_t g_wF4[384];                   // B fragments (half2) conv4 1x1 (48-co pad)
__device__ float g_s2[16], g_s3[16];

// ---------------- PTX helpers ----------------
__device__ __forceinline__ uint32_t s2u(const void* p) {
    uint32_t a;
    asm("{ .reg .u64 t; cvta.to.shared.u64 t, %1; cvt.u32.u64 %0, t; }" : "=r"(a) : "l"(p));
    return a;
}
__device__ __forceinline__ void cpasync16(uint32_t dst, const void* src) {
    asm volatile("cp.async.cg.shared.global [%0], [%1], 16;" :: "r"(dst), "l"(src));
}
__device__ __forceinline__ void cp_commit() {
    asm volatile("cp.async.commit_group;" ::: "memory");
}
template<int N> __device__ __forceinline__ void cp_wait() {
    asm volatile("cp.async.wait_group %0;" :: "n"(N) : "memory");
}
__device__ __forceinline__ void sts_zero16(uint32_t dst) {
    asm volatile("st.shared.v4.u32 [%0], {%1,%1,%1,%1};" :: "r"(dst), "r"(0u) : "memory");
}
__device__ __forceinline__ void ldmatrix_x4(uint32_t& r0, uint32_t& r1, uint32_t& r2,
                                            uint32_t& r3, uint32_t addr) {
    asm volatile("ldmatrix.sync.aligned.m8n8.x4.shared.b16 {%0,%1,%2,%3}, [%4];"
                 : "=r"(r0), "=r"(r1), "=r"(r2), "=r"(r3) : "r"(addr));
}
__device__ __forceinline__ void mma_f16(float* d, uint32_t a0, uint32_t a1, uint32_t a2,
                                        uint32_t a3, uint32_t b0, uint32_t b1) {
    asm volatile(
        "mma.sync.aligned.m16n8k16.row.col.f32.f16.f16.f32 "
        "{%0,%1,%2,%3}, {%4,%5,%6,%7}, {%8,%9}, {%0,%1,%2,%3};"
        : "+f"(d[0]), "+f"(d[1]), "+f"(d[2]), "+f"(d[3])
        : "r"(a0), "r"(a1), "r"(a2), "r"(a3), "r"(b0), "r"(b1));
}
__device__ __forceinline__ uint32_t pack_h2(float a, float b) {
    __half2 h = __floats2half2_rn(a, b);
    return *reinterpret_cast<uint32_t*>(&h);
}

// ---------------- prep: fold BN into conv weights, build B fragments ----------------
__global__ void prep_kernel(
    const float* __restrict__ w1, const float* __restrict__ g1, const float* __restrict__ b1,
    const float* __restrict__ rm1, const float* __restrict__ rv1,
    const float* __restrict__ w2, const float* __restrict__ g2, const float* __restrict__ b2,
    const float* __restrict__ rm2, const float* __restrict__ rv2,
    const float* __restrict__ w3, const float* __restrict__ g3, const float* __restrict__ b3,
    const float* __restrict__ rm3, const float* __restrict__ rv3,
    const float* __restrict__ w4)
{
    int tid = threadIdx.x;
    if (tid == 0) { g_dsum = 0.0; g_dssq = 0.0; }

    for (int i = tid; i < 144; i += 256) {
        int o = i / 9, k = i % 9;
        float sc = g1[o] / sqrtf(rv1[o] + 1e-5f);
        float s = 0.f;
        #pragma unroll
        for (int t = 0; t < TT; t++) s += w1[(o * TT + t) * 9 + k];
        g_w1f[i] = sc * s;
    }
    if (tid < 16) {
        float sc1 = g1[tid] / sqrtf(rv1[tid] + 1e-5f);
        g_s1[tid] = b1[tid] - rm1[tid] * sc1;
        float sc2 = g2[tid] / sqrtf(rv2[tid] + 1e-5f);
        g_s2[tid] = b2[tid] - rm2[tid] * sc2;
        float sc3 = g3[tid] / sqrtf(rv3[tid] + 1e-5f);
        g_s3[tid] = b3[tid] - rm3[tid] * sc3;
    }
    // B fragments for m16n8k16 (conv2/conv3): thread t, reg r(k-half), ngroup g, tap
    for (int i = tid; i < 1152; i += 256) {
        int t = i & 31, r = (i >> 5) & 1, g = (i >> 6) & 1, tap = i >> 7;
        int co = (g << 3) + (t >> 2);
        int k0 = (t & 3) * 2 + (r << 3);
        float sc2 = g2[co] / sqrtf(rv2[co] + 1e-5f);
        g_wF2[i] = pack_h2(sc2 * w2[((co * 16 + k0) * 9) + tap],
                           sc2 * w2[((co * 16 + k0 + 1) * 9) + tap]);
        float sc3 = g3[co] / sqrtf(rv3[co] + 1e-5f);
        g_wF3[i] = pack_h2(sc3 * w3[((co * 16 + k0) * 9) + tap],
                           sc3 * w3[((co * 16 + k0 + 1) * 9) + tap]);
    }
    // conv4 1x1 fragments: 6 n-chunks of 8 co (45 real, 3 zero-pad), K=16
    for (int i = tid; i < 384; i += 256) {
        int t = i & 31, r = (i >> 5) & 1, n = i >> 6;
        int co = (n << 3) + (t >> 2);
        int k0 = (t & 3) * 2 + (r << 3);
        float v0 = (co < 45) ? w4[co * 16 + k0]     : 0.f;
        float v1 = (co < 45) ? w4[co * 16 + k0 + 1] : 0.f;
        g_wF4[i] = pack_h2(v0, v1);
    }
}

// ---------------- acc = sum|raw_diff| + mean/var reduction ----------------
__global__ void accum_kernel(const float* __restrict__ rd)
{
    int i = blockIdx.x * 256 + threadIdx.x;
    int b = i >> 16;
    int r = i & 65535;
    const float4* p = (const float4*)rd;
    float4 a = make_float4(0.f, 0.f, 0.f, 0.f);
    #pragma unroll
    for (int t = 0; t < TT - 1; t++) {
        float4 v = p[((size_t)(b * (TT - 1) + t)) * 65536 + r];
        a.x += fabsf(v.x); a.y += fabsf(v.y); a.z += fabsf(v.z); a.w += fabsf(v.w);
    }
    ((float4*)g_acc)[i] = a;

    double ls  = (double)a.x + (double)a.y + (double)a.z + (double)a.w;
    double lss = (double)a.x * a.x + (double)a.y * a.y + (double)a.z * a.z + (double)a.w * a.w;
    #pragma unroll
    for (int o = 16; o > 0; o >>= 1) {
        ls  += __shfl_down_sync(0xffffffffu, ls,  o);
        lss += __shfl_down_sync(0xffffffffu, lss, o);
    }
    __shared__ double ss[8], sq[8];
    int wid = threadIdx.x >> 5, lane = threadIdx.x & 31;
    if (lane == 0) { ss[wid] = ls; sq[wid] = lss; }
    __syncthreads();
    if (threadIdx.x == 0) {
        double s = 0.0, q = 0.0;
        #pragma unroll
        for (int w = 0; w < 8; w++) { s += ss[w]; q += sq[w]; }
        atomicAdd(&g_dsum, s);
        atomicAdd(&g_dssq, q);
    }
}

__global__ void finalize_kernel()
{
    double n = (double)NPIX;
    double mean = g_dsum / n;
    double var = (g_dssq - g_dsum * g_dsum / n) / (n - 1.0);
    double sd = sqrt(var);
    g_mean = (float)mean;
    g_inv = (float)(1.0 / (sd + 1e-6));
}

// ---------------- conv1: 1->16 chan, 3x3 d1, fp16 NHWC output ----------------
__global__ void conv1_kernel()
{
    __shared__ float sw[144], sb[16];
    int tid = threadIdx.x;
    if (tid < 144) sw[tid] = g_w1f[tid];
    if (tid < 16)  sb[tid] = g_s1[tid];
    __syncthreads();

    int p = blockIdx.x * 256 + tid;
    int b = p >> 18;
    int rem = p & (HW - 1);
    int y = rem >> 9, x = rem & 511;
    float mean = g_mean, inv = g_inv;

    float m[9];
    #pragma unroll
    for (int ky = 0; ky < 3; ky++) {
        #pragma unroll
        for (int kx = 0; kx < 3; kx++) {
            int yy = y + ky - 1, xx = x + kx - 1;
            bool ok = (yy >= 0) & (yy < HH) & (xx >= 0) & (xx < WW);
            m[ky * 3 + kx] = ok ? (g_acc[(b << 18) + (yy << 9) + xx] - mean) * inv : 0.f;
        }
    }
    float v[16];
    #pragma unroll
    for (int o = 0; o < 16; o++) {
        float s = sb[o];
        #pragma unroll
        for (int k = 0; k < 9; k++) s = fmaf(sw[o * 9 + k], m[k], s);
        v[o] = fmaxf(s, 0.f);
    }
    uint4* out = (uint4*)(g_h1 + (size_t)p * 16);
    out[0] = make_uint4(pack_h2(v[0], v[1]),  pack_h2(v[2], v[3]),
                        pack_h2(v[4], v[5]),  pack_h2(v[6], v[7]));
    out[1] = make_uint4(pack_h2(v[8], v[9]),  pack_h2(v[10], v[11]),
                        pack_h2(v[12], v[13]), pack_h2(v[14], v[15]));
}

// ---------------- conv2/conv3 via ldmatrix + mma.sync (fp16 in, fp32 acc) ----------------
template<int DIL>
__global__ __launch_bounds__(256) void conv16_hmma_kernel()
{
    constexpr int XW = 128, YR = 64, PD = 2;
    constexpr int RING = 2 * DIL + PD + 1;
    constexpr int SEGPX = XW + 2 * DIL;
    constexpr int SLOTB = SEGPX * 48;

    const __half* __restrict__ in  = (DIL == 2) ? g_h1 : g_h2;
    __half*       __restrict__ out = (DIL == 2) ? g_h2 : g_h1;
    const uint32_t* __restrict__ wF = (DIL == 2) ? g_wF2 : g_wF3;
    const float* __restrict__ sB   = (DIL == 2) ? g_s2  : g_s3;

    extern __shared__ char smem[];
    uint32_t sbase = s2u(smem);
    int tid = threadIdx.x;
    int warp = tid >> 5, lane = tid & 31;
    int x0 = blockIdx.x * XW;
    int y0 = blockIdx.y * YR;
    int b  = blockIdx.z;
    const __half* gin = in + (((size_t)b) << 18) * 16;

    uint32_t bw[9][2][2];
    #pragma unroll
    for (int tap = 0; tap < 9; tap++)
        #pragma unroll
        for (int g = 0; g < 2; g++)
            #pragma unroll
            for (int r = 0; r < 2; r++)
                bw[tap][g][r] = wF[(((tap << 1) + g) << 1 | r) * 32 + lane];

    float bc0[2], bc1[2];
    #pragma unroll
    for (int g = 0; g < 2; g++) {
        int c = (g << 3) + ((lane & 3) << 1);
        bc0[g] = sB[c]; bc1[g] = sB[c + 1];
    }

    int prow = warp * 16 + (lane & 7) + ((lane >> 3) & 1) * 8;
    int sel16 = ((lane >> 4) & 1) * 16;

    auto load_row = [&](int idx) {
        if (idx <= YR - 1 + 2 * DIL) {
            int r = y0 - DIL + idx;
            uint32_t dbase = sbase + (idx % RING) * SLOTB;
            bool rok = (r >= 0) & (r < HH);
            const __half* grow = gin + (((size_t)r) << 9) * 16;
            for (int c = tid; c < SEGPX * 2; c += 256) {
                int s = c >> 1, part = c & 1;
                int x = x0 - DIL + s;
                uint32_t dst = dbase + s * 48 + part * 16;
                if (rok && (unsigned)x < (unsigned)WW)
                    cpasync16(dst, grow + x * 16 + part * 8);
                else
                    sts_zero16(dst);
            }
        }
        cp_commit();
    };

    for (int idx = 0; idx <= 2 * DIL + PD; idx++) load_row(idx);

    for (int i = 0; i < YR; i++) {
        cp_wait<PD>();
        __syncthreads();

        float d[2][4];
        #pragma unroll
        for (int g = 0; g < 2; g++)
            #pragma unroll
            for (int r = 0; r < 4; r++) d[g][r] = 0.f;

        #pragma unroll
        for (int ky = 0; ky < 3; ky++) {
            uint32_t abase = sbase + ((i + ky * DIL) % RING) * SLOTB;
            #pragma unroll
            for (int kx = 0; kx < 3; kx++) {
                uint32_t a0, a1, a2, a3;
                ldmatrix_x4(a0, a1, a2, a3, abase + (prow + kx * DIL) * 48 + sel16);
                int tap = ky * 3 + kx;
                mma_f16(d[0], a0, a1, a2, a3, bw[tap][0][0], bw[tap][0][1]);
                mma_f16(d[1], a0, a1, a2, a3, bw[tap][1][0], bw[tap][1][1]);
            }
        }

        __half* orow = out + ((((size_t)b << 18) + ((size_t)(y0 + i) << 9) + x0 + warp * 16)) * 16;
        int px = (lane >> 2);
        #pragma unroll
        for (int g = 0; g < 2; g++) {
            int c = (g << 3) + ((lane & 3) << 1);
            uint32_t lo = pack_h2(fmaxf(d[g][0] + bc0[g], 0.f), fmaxf(d[g][1] + bc1[g], 0.f));
            uint32_t hi = pack_h2(fmaxf(d[g][2] + bc0[g], 0.f), fmaxf(d[g][3] + bc1[g], 0.f));
            *(uint32_t*)(orow + px * 16 + c)       = lo;
            *(uint32_t*)(orow + (px + 8) * 16 + c) = hi;
        }

        __syncthreads();
        load_row(i + 2 * DIL + PD + 1);
    }
}

// ---------------- final: conv4 1x1 via HMMA + sigmoid + dynamic 3x3 filtering ----------------
// 256 threads = 8 warps; each warp: 16 contiguous pixels of one row.
__global__ __launch_bounds__(256) void final_mma_kernel(
    const float* __restrict__ x, const float* __restrict__ biasp,
    float* __restrict__ out)
{
    __shared__ float sker[8][16][52];   // [warp][px][48 co + pad]

    int tid = threadIdx.x;
    int warp = tid >> 5, lane = tid & 31;
    int pbase = blockIdx.x * 128 + warp * 16;
    int b = pbase >> 18;
    int rem = pbase & (HW - 1);
    int y = rem >> 9, xb0 = rem & 511;

    // B fragments (w4)
    uint32_t bw[6][2];
    #pragma unroll
    for (int n = 0; n < 6; n++) {
        bw[n][0] = g_wF4[(n * 2 + 0) * 32 + lane];
        bw[n][1] = g_wF4[(n * 2 + 1) * 32 + lane];
    }

    // A fragments straight from global NHWC fp16
    const __half* hb = g_h1 + (size_t)pbase * 16;
    int arow = lane >> 2;
    int cc = (lane & 3) * 2;
    uint32_t a0 = *(const uint32_t*)(hb + arow * 16 + cc);
    uint32_t a1 = *(const uint32_t*)(hb + (arow + 8) * 16 + cc);
    uint32_t a2 = *(const uint32_t*)(hb + arow * 16 + cc + 8);
    uint32_t a3 = *(const uint32_t*)(hb + (arow + 8) * 16 + cc + 8);

    float d[6][4];
    #pragma unroll
    for (int n = 0; n < 6; n++)
        #pragma unroll
        for (int r = 0; r < 4; r++) d[n][r] = 0.f;
    #pragma unroll
    for (int n = 0; n < 6; n++)
        mma_f16(d[n], a0, a1, a2, a3, bw[n][0], bw[n][1]);

    float bias = biasp[0];
    // sigmoid -> per-warp smem kernel tile
    #pragma unroll
    for (int n = 0; n < 6; n++) {
        int col = n * 8 + cc;
        #pragma unroll
        for (int half = 0; half < 2; half++) {           // rows arow / arow+8
            int px = arow + half * 8;
            float z0 = d[n][half * 2 + 0] + bias;
            float z1 = d[n][half * 2 + 1] + bias;
            float k0 = fmaf(10.f, 1.f / (1.f + __expf(-z0)), 0.1f);
            float k1 = fmaf(10.f, 1.f / (1.f + __expf(-z1)), 0.1f);
            sker[warp][px][col]     = k0;
            sker[warp][px][col + 1] = k1;
        }
    }
    __syncwarp();

    // dynamic filtering: lanes 0-15 -> t=0..2, lanes 16-31 -> t=3,4 (same 16 px)
    int px = lane & 15;
    int grp = lane >> 4;
    int gx = xb0 + px;
    const float* kp = sker[warp][px];
    int tlo = grp ? 3 : 0;
    int thi = grp ? 5 : 3;
    for (int t = tlo; t < thi; t++) {
        const float* xp = x + ((size_t)(b * TT + t) << 18);
        float o = 0.f;
        #pragma unroll
        for (int dy = 0; dy < 3; dy++) {
            int yy = y + dy - 1;
            bool yok = (yy >= 0) & (yy < HH);
            #pragma unroll
            for (int dx = 0; dx < 3; dx++) {
                int xx = gx + dx - 1;
                bool ok = yok & (xx >= 0) & (xx < WW);
                float xv = ok ? xp[(yy << 9) + xx] : 0.f;
                o = fmaf(kp[t * 9 + dy * 3 + dx], xv, o);
            }
        }
        out[((size_t)(b * TT + t) << 18) + (y << 9) + gx] = o;
    }
}

// ---------------- launch ----------------
extern "C" void kernel_launch(void* const* d_in, const int* in_sizes, int n_in,
                              void* d_out, int out_size)
{
    const float* x_aligned = (const float*)d_in[0];
    const float* raw_diff  = (const float*)d_in[1];
    const float* w1  = (const float*)d_in[2];
    const float* g1  = (const float*)d_in[3];
    const float* b1  = (const float*)d_in[4];
    const float* rm1 = (const float*)d_in[5];
    const float* rv1 = (const float*)d_in[6];
    const float* w2  = (const float*)d_in[7];
    const float* g2  = (const float*)d_in[8];
    const float* b2  = (const float*)d_in[9];
    const float* rm2 = (const float*)d_in[10];
    const float* rv2 = (const float*)d_in[11];
    const float* w3  = (const float*)d_in[12];
    const float* g3  = (const float*)d_in[13];
    const float* b3  = (const float*)d_in[14];
    const float* rm3 = (const float*)d_in[15];
    const float* rv3 = (const float*)d_in[16];
    const float* w4  = (const float*)d_in[17];
    const float* bias = (const float*)d_in[18];
    float* out = (float*)d_out;

    const int SMEM2 = 7  * (132 * 48);   // 44,352 B
    const int SMEM4 = 11 * (136 * 48);   // 71,808 B
    static bool attr_done = false;
    if (!attr_done) {
        cudaFuncSetAttribute(conv16_hmma_kernel<2>, cudaFuncAttributeMaxDynamicSharedMemorySize, SMEM2);
        cudaFuncSetAttribute(conv16_hmma_kernel<4>, cudaFuncAttributeMaxDynamicSharedMemorySize, SMEM4);
        attr_done = true;
    }

    prep_kernel<<<1, 256>>>(w1, g1, b1, rm1, rv1, w2, g2, b2, rm2, rv2,
                            w3, g3, b3, rm3, rv3, w4);
    accum_kernel<<<NPIX / 4 / 256, 256>>>(raw_diff);
    finalize_kernel<<<1, 1>>>();
    conv1_kernel<<<NPIX / 256, 256>>>();
    {
        dim3 grd(WW / 128, HH / 64, BB);   // (4, 8, 8)
        conv16_hmma_kernel<2><<<grd, 256, SMEM2>>>();
        conv16_hmma_kernel<4><<<grd, 256, SMEM4>>>();
    }
    final_mma_kernel<<<NPIX / 128, 256>>>(x_aligned, bias, out);
}